// round 2
// baseline (speedup 1.0000x reference)
#include <cuda_runtime.h>
#include <math.h>

// Inputs (metadata order):
//   d_in[0]: z          float32, 50000*512
//   d_in[1]: edge_index int32 (JAX downcasts int64 without x64), 2*150000
// Output: float32, 150000

#define D 512
#define EPS 1e-6f

__global__ void edge_dist_kernel(const float* __restrict__ z,
                                 const int* __restrict__ ei,
                                 float* __restrict__ out,
                                 int n_edges) {
    int warp = (blockIdx.x * blockDim.x + threadIdx.x) >> 5;
    int lane = threadIdx.x & 31;
    if (warp >= n_edges) return;

    int ia = ei[warp];
    int ib = ei[n_edges + warp];

    const float4* __restrict__ A = (const float4*)(z + (long long)ia * D);
    const float4* __restrict__ B = (const float4*)(z + (long long)ib * D);

    float dot = 0.f, na2 = 0.f, nb2 = 0.f, sa = 0.f, sb = 0.f;

#pragma unroll
    for (int i = 0; i < 4; i++) {
        float4 a = A[lane + 32 * i];
        float4 b = B[lane + 32 * i];
        dot += a.x * b.x + a.y * b.y + a.z * b.z + a.w * b.w;
        na2 += a.x * a.x + a.y * a.y + a.z * a.z + a.w * a.w;
        nb2 += b.x * b.x + b.y * b.y + b.z * b.z + b.w * b.w;
        sa  += a.x + a.y + a.z + a.w;
        sb  += b.x + b.y + b.z + b.w;
    }

#pragma unroll
    for (int off = 16; off > 0; off >>= 1) {
        dot += __shfl_xor_sync(0xFFFFFFFFu, dot, off);
        na2 += __shfl_xor_sync(0xFFFFFFFFu, na2, off);
        nb2 += __shfl_xor_sync(0xFFFFFFFFu, nb2, off);
        sa  += __shfl_xor_sync(0xFFFFFFFFu, sa,  off);
        sb  += __shfl_xor_sync(0xFFFFFFFFu, sb,  off);
    }

    if (lane == 0) {
        float na = sqrtf(na2);
        float nb = sqrtf(nb2);
        // ||a/na - b/nb + eps||^2 expanded:
        float d2 = 2.0f
                 - 2.0f * dot / (na * nb)
                 + 2.0f * EPS * (sa / na - sb / nb)
                 + (float)D * EPS * EPS;
        d2 = fmaxf(d2, 0.0f);
        float v = 1.0f - sqrtf(d2);
        out[warp] = 1.0f / (1.0f + expf(-v));
    }
}

extern "C" void kernel_launch(void* const* d_in, const int* in_sizes, int n_in,
                              void* d_out, int out_size) {
    const float* z = (const float*)d_in[0];
    const int* ei = (const int*)d_in[1];
    float* out = (float*)d_out;
    int n_edges = out_size;  // 150000

    int threads = 256;                       // 8 warps/block, 1 edge/warp
    long long total_threads = (long long)n_edges * 32;
    int blocks = (int)((total_threads + threads - 1) / threads);
    edge_dist_kernel<<<blocks, threads>>>(z, ei, out, n_edges);
}